// round 1
// baseline (speedup 1.0000x reference)
#include <cuda_runtime.h>
#include <math.h>

// Problem constants (fixed by the dataset: B=2,S=2048 -> T=4096; H=1024; F=4096; E=8; TOP_K=2)
#define Tt 4096
#define Hh 1024
#define Ff 4096
#define Ee 8

// ---------------- scratch (static device globals; no allocation) ----------------
// unified mid buffer: rows [0,T) = base FFN mid; rows [T, T+2T) = expert assignment mids
__device__ float  g_mid[(size_t)3 * Tt * Ff];      // ~201 MB
__device__ float  g_expout[(size_t)2 * Tt * Hh];   // ~33.5 MB (unweighted expert outputs)
__device__ int    g_tok[Ee * Tt];                  // token id per (expert, slot)
__device__ int    g_cnt[Ee];
__device__ int    g_off[Ee];
__device__ int4   g_sel[Tt];                       // (e0, slot0, e1, slot1) per token
__device__ float2 g_wt[Tt];                        // renormalized top-2 weights

// ---------------- helpers ----------------
__device__ __forceinline__ unsigned f2tf(float f) {
    unsigned u;
    asm("cvt.rna.tf32.f32 %0, %1;" : "=r"(u) : "f"(f));
    return u;
}

__device__ __forceinline__ void mma8(float* c, const unsigned* a, const unsigned* b) {
    asm volatile(
        "mma.sync.aligned.m16n8k8.row.col.f32.tf32.tf32.f32 "
        "{%0,%1,%2,%3}, {%4,%5,%6,%7}, {%8,%9}, {%0,%1,%2,%3};"
        : "+f"(c[0]), "+f"(c[1]), "+f"(c[2]), "+f"(c[3])
        : "r"(a[0]), "r"(a[1]), "r"(a[2]), "r"(a[3]),
          "r"(b[0]), "r"(b[1]));
}

// ---------------- small kernels ----------------
__global__ void zero_cnt_kernel() {
    if (threadIdx.x < Ee) g_cnt[threadIdx.x] = 0;
}

// one warp per token: logits = x @ router_w, softmax, top2, renormalize, assign slots
__global__ void router_kernel(const float* __restrict__ x, const float* __restrict__ rw) {
    int wid  = threadIdx.x >> 5;
    int lane = threadIdx.x & 31;
    int t = blockIdx.x * 8 + wid;
    if (t >= Tt) return;

    float acc[8] = {0.f, 0.f, 0.f, 0.f, 0.f, 0.f, 0.f, 0.f};
    const float* xr = x + (size_t)t * Hh;
    for (int h = lane; h < Hh; h += 32) {
        float xv = xr[h];
        float4 r0 = *(const float4*)(rw + (size_t)h * Ee);
        float4 r1 = *(const float4*)(rw + (size_t)h * Ee + 4);
        acc[0] += xv * r0.x; acc[1] += xv * r0.y; acc[2] += xv * r0.z; acc[3] += xv * r0.w;
        acc[4] += xv * r1.x; acc[5] += xv * r1.y; acc[6] += xv * r1.z; acc[7] += xv * r1.w;
    }
#pragma unroll
    for (int e = 0; e < 8; e++)
#pragma unroll
        for (int o = 16; o > 0; o >>= 1)
            acc[e] += __shfl_xor_sync(0xffffffffu, acc[e], o);

    if (lane == 0) {
        float m = acc[0];
#pragma unroll
        for (int e = 1; e < 8; e++) m = fmaxf(m, acc[e]);
        float p[8];
#pragma unroll
        for (int e = 0; e < 8; e++) p[e] = expf(acc[e] - m);
        // top-2, ties -> lower index first (matches jax top_k)
        int i0 = 0; float b0 = p[0];
#pragma unroll
        for (int e = 1; e < 8; e++) if (p[e] > b0) { b0 = p[e]; i0 = e; }
        int i1 = -1; float b1 = -1.f;
#pragma unroll
        for (int e = 0; e < 8; e++) if (e != i0 && p[e] > b1) { b1 = p[e]; i1 = e; }
        float inv = 1.f / (b0 + b1);
        int s0 = atomicAdd(&g_cnt[i0], 1); g_tok[i0 * Tt + s0] = t;
        int s1 = atomicAdd(&g_cnt[i1], 1); g_tok[i1 * Tt + s1] = t;
        g_sel[t] = make_int4(i0, s0, i1, s1);
        g_wt[t]  = make_float2(b0 * inv, b1 * inv);
    }
}

__global__ void scan_kernel() {
    if (threadIdx.x == 0) {
        int o = 0;
        for (int e = 0; e < Ee; e++) { g_off[e] = o; o += g_cnt[e]; }
    }
}

// ---------------- grouped GEMM ----------------
// MODE 1: mid = silu(X @ W1)   [K=H, N=F], A rows gathered from x per group
// MODE 2: out = mid @ W2       [K=F, N=H], base -> d_out, experts -> g_expout
template <int MODE>
__global__ void __launch_bounds__(256) gemm_kernel(
    const float* __restrict__ Xin,
    const float* __restrict__ Wbase,
    const float* __restrict__ Wexp,
    float* __restrict__ Dout)
{
    constexpr int Kd = (MODE == 1) ? Hh : Ff;
    constexpr int Nd = (MODE == 1) ? Ff : Hh;

    const int g  = blockIdx.z;
    const int tm = blockIdx.x;
    const int tn = blockIdx.y;
    const int e  = g - 1;
    const int cnt = (g == 0) ? Tt : g_cnt[e];
    if (tm * 128 >= cnt) return;

    const float* Bsrc = (g == 0) ? Wbase : (Wexp + (size_t)e * Kd * Nd);
    const float* Ap   = (MODE == 1) ? Xin : (const float*)g_mid;
    float* Outp;
    int ldo;
    if (MODE == 1) { Outp = g_mid; ldo = Ff; }
    else           { Outp = (g == 0) ? Dout : g_expout; ldo = Hh; }

    __shared__ unsigned As[128 * 36];   // stride 36 -> conflict-free frag loads
    __shared__ unsigned Bs[32 * 136];   // stride 136 -> conflict-free frag loads
    __shared__ int s_arow[128];
    __shared__ int s_orow[128];

    const int tid = threadIdx.x;
    if (tid < 128) {
        int idx = tm * 128 + tid;
        int arow = -1, orow = -1;
        if (idx < cnt) {
            if (g == 0) { arow = idx; orow = idx; }
            else {
                int tok = g_tok[e * Tt + idx];
                int p   = g_off[e] + idx;
                if (MODE == 1) { arow = tok;      orow = Tt + p; }
                else           { arow = Tt + p;   orow = p; }
            }
        }
        s_arow[tid] = arow;
        s_orow[tid] = orow;
    }
    __syncthreads();

    float C[4][4][4];
#pragma unroll
    for (int i = 0; i < 4; i++)
#pragma unroll
        for (int j = 0; j < 4; j++)
#pragma unroll
            for (int q = 0; q < 4; q++) C[i][j][q] = 0.f;

    const int ar  = tid >> 3;          // A load: row within 32-row pass
    const int ac  = (tid & 7) * 4;     // A load: 4-float column group
    const int bkr = tid >> 5;          // B load: k-row within 8-row pass
    const int bc  = (tid & 31) * 4;    // B load: 4-float column group
    const int lane = tid & 31;
    const int wid  = tid >> 5;
    const int wm = wid & 1, wn = wid >> 1;   // warp grid 2 (m) x 4 (n)
    const int g8 = lane >> 2, tq = lane & 3;

    for (int k0 = 0; k0 < Kd; k0 += 32) {
        float4 va[4], vb[4];
#pragma unroll
        for (int p = 0; p < 4; p++) {
            int r = p * 32 + ar;
            int src = s_arow[r];
            va[p] = (src >= 0)
                ? *(const float4*)(Ap + (size_t)src * Kd + k0 + ac)
                : make_float4(0.f, 0.f, 0.f, 0.f);
        }
#pragma unroll
        for (int p = 0; p < 4; p++) {
            int kr = p * 8 + bkr;
            vb[p] = *(const float4*)(Bsrc + (size_t)(k0 + kr) * Nd + tn * 128 + bc);
        }
        __syncthreads();   // previous tile's compute done
#pragma unroll
        for (int p = 0; p < 4; p++) {
            int r = p * 32 + ar;
            unsigned* d = &As[r * 36 + ac];
            d[0] = f2tf(va[p].x); d[1] = f2tf(va[p].y);
            d[2] = f2tf(va[p].z); d[3] = f2tf(va[p].w);
        }
#pragma unroll
        for (int p = 0; p < 4; p++) {
            int kr = p * 8 + bkr;
            unsigned* d = &Bs[kr * 136 + bc];
            d[0] = f2tf(vb[p].x); d[1] = f2tf(vb[p].y);
            d[2] = f2tf(vb[p].z); d[3] = f2tf(vb[p].w);
        }
        __syncthreads();

#pragma unroll
        for (int kk = 0; kk < 32; kk += 8) {
            unsigned a[4][4], b[4][2];
#pragma unroll
            for (int i = 0; i < 4; i++) {
                int r = wm * 64 + i * 16 + g8;
                a[i][0] = As[r * 36 + kk + tq];
                a[i][1] = As[(r + 8) * 36 + kk + tq];
                a[i][2] = As[r * 36 + kk + tq + 4];
                a[i][3] = As[(r + 8) * 36 + kk + tq + 4];
            }
#pragma unroll
            for (int j = 0; j < 4; j++) {
                int cc = wn * 32 + j * 8 + g8;
                b[j][0] = Bs[(kk + tq) * 136 + cc];
                b[j][1] = Bs[(kk + tq + 4) * 136 + cc];
            }
#pragma unroll
            for (int i = 0; i < 4; i++)
#pragma unroll
                for (int j = 0; j < 4; j++)
                    mma8(C[i][j], a[i], b[j]);
        }
    }

    // epilogue
#pragma unroll
    for (int i = 0; i < 4; i++) {
        int r0 = wm * 64 + i * 16 + g8;
        int o0 = s_orow[r0];
        int o1 = s_orow[r0 + 8];
#pragma unroll
        for (int j = 0; j < 4; j++) {
            int col = tn * 128 + wn * 32 + j * 8 + 2 * tq;
            float v0 = C[i][j][0], v1 = C[i][j][1];
            float v2 = C[i][j][2], v3 = C[i][j][3];
            if (MODE == 1) {
                v0 = v0 / (1.f + __expf(-v0));
                v1 = v1 / (1.f + __expf(-v1));
                v2 = v2 / (1.f + __expf(-v2));
                v3 = v3 / (1.f + __expf(-v3));
            }
            if (o0 >= 0) *(float2*)(Outp + (size_t)o0 * ldo + col) = make_float2(v0, v1);
            if (o1 >= 0) *(float2*)(Outp + (size_t)o1 * ldo + col) = make_float2(v2, v3);
        }
    }
}

// out[t] = base_out[t] (already in d_out) + w0*expout[p0] + w1*expout[p1]
__global__ void combine_kernel(float* __restrict__ out) {
    int t = blockIdx.x;
    int4 s = g_sel[t];
    float2 w = g_wt[t];
    int p0 = g_off[s.x] + s.y;
    int p1 = g_off[s.z] + s.w;
    const float4* a = (const float4*)(g_expout + (size_t)p0 * Hh);
    const float4* b = (const float4*)(g_expout + (size_t)p1 * Hh);
    float4* o = (float4*)(out + (size_t)t * Hh);
    int i = threadIdx.x;   // 256 threads * 4 floats = H
    float4 ov = o[i], av = a[i], bv = b[i];
    ov.x += w.x * av.x + w.y * bv.x;
    ov.y += w.x * av.y + w.y * bv.y;
    ov.z += w.x * av.z + w.y * bv.z;
    ov.w += w.x * av.w + w.y * bv.w;
    o[i] = ov;
}

// ---------------- launch ----------------
extern "C" void kernel_launch(void* const* d_in, const int* in_sizes, int n_in,
                              void* d_out, int out_size)
{
    const float* x   = (const float*)d_in[0];
    const float* rw  = (const float*)d_in[1];
    const float* bw1 = (const float*)d_in[2];
    const float* bw2 = (const float*)d_in[3];
    const float* ew1 = (const float*)d_in[4];
    const float* ew2 = (const float*)d_in[5];
    float* out = (float*)d_out;

    zero_cnt_kernel<<<1, 32>>>();
    router_kernel<<<Tt / 8, 256>>>(x, rw);
    scan_kernel<<<1, 32>>>();

    // GEMM1: mid = silu(X @ W1)   grid: (m_tiles=32, n_tiles=F/128, groups=9)
    gemm_kernel<1><<<dim3(32, Ff / 128, Ee + 1), 256>>>(x, bw1, ew1, nullptr);
    // GEMM2: out = mid @ W2       grid: (m_tiles=32, n_tiles=H/128, groups=9)
    gemm_kernel<2><<<dim3(32, Hh / 128, Ee + 1), 256>>>(nullptr, bw2, ew2, out);

    combine_kernel<<<Tt, 256>>>(out);
}

// round 3
// speedup vs baseline: 1.1420x; 1.1420x over previous
#include <cuda_runtime.h>
#include <math.h>

// Problem constants (B=2,S=2048 -> T=4096; H=1024; F=4096; E=8; TOP_K=2)
#define Tt 4096
#define Hh 1024
#define Ff 4096
#define Ee 8

// ---------------- scratch (static device globals; no allocation) ----------------
// g_mid rows: [0,T) = base mid; [T, 3T) = expert-assignment mids (by p = off[e]+slot)
__device__ float  g_mid[(size_t)3 * Tt * Ff];      // ~201 MB (stored tf32-rounded)
__device__ float  g_xtf[(size_t)Tt * Hh];          // x pre-rounded to tf32
__device__ float  g_xg [(size_t)2 * Tt * Hh];      // gathered expert A rows (tf32-rounded)
__device__ float  g_expout[(size_t)2 * Tt * Hh];   // unweighted expert outputs
__device__ int    g_tok[Ee * Tt];
__device__ int    g_cnt[Ee];
__device__ int    g_off[Ee];
__device__ int4   g_sel[Tt];                       // (e0, slot0, e1, slot1)
__device__ float2 g_wt[Tt];

// ---------------- helpers ----------------
__device__ __forceinline__ unsigned f2tf(float f) {
    unsigned u;
    asm("cvt.rna.tf32.f32 %0, %1;" : "=r"(u) : "f"(f));
    return u;
}
__device__ __forceinline__ unsigned f2tf_u(unsigned raw) {
    unsigned u;
    asm("cvt.rna.tf32.f32 %0, %1;" : "=r"(u) : "f"(__uint_as_float(raw)));
    return u;
}

__device__ __forceinline__ void mma8(float* c, const unsigned* a, const unsigned* b) {
    asm volatile(
        "mma.sync.aligned.m16n8k8.row.col.f32.tf32.tf32.f32 "
        "{%0,%1,%2,%3}, {%4,%5,%6,%7}, {%8,%9}, {%0,%1,%2,%3};"
        : "+f"(c[0]), "+f"(c[1]), "+f"(c[2]), "+f"(c[3])
        : "r"(a[0]), "r"(a[1]), "r"(a[2]), "r"(a[3]),
          "r"(b[0]), "r"(b[1]));
}

__device__ __forceinline__ void cp16(unsigned smem_addr, const void* gptr, int srcsize) {
    asm volatile("cp.async.cg.shared.global [%0], [%1], 16, %2;"
                 :: "r"(smem_addr), "l"(gptr), "r"(srcsize));
}
__device__ __forceinline__ void cp_commit() {
    asm volatile("cp.async.commit_group;");
}
template <int N>
__device__ __forceinline__ void cp_wait() {
    asm volatile("cp.async.wait_group %0;" :: "n"(N));
}

// ---------------- small kernels ----------------
__global__ void zero_cnt_kernel() {
    if (threadIdx.x < Ee) g_cnt[threadIdx.x] = 0;
}

// one warp per token: logits, softmax, top2, renormalize, slot assignment
__global__ void router_kernel(const float* __restrict__ x, const float* __restrict__ rw) {
    int wid  = threadIdx.x >> 5;
    int lane = threadIdx.x & 31;
    int t = blockIdx.x * 8 + wid;
    if (t >= Tt) return;

    float acc[8] = {0.f,0.f,0.f,0.f,0.f,0.f,0.f,0.f};
    const float* xr = x + (size_t)t * Hh;
    for (int h = lane; h < Hh; h += 32) {
        float xv = xr[h];
        float4 r0 = *(const float4*)(rw + (size_t)h * Ee);
        float4 r1 = *(const float4*)(rw + (size_t)h * Ee + 4);
        acc[0] += xv * r0.x; acc[1] += xv * r0.y; acc[2] += xv * r0.z; acc[3] += xv * r0.w;
        acc[4] += xv * r1.x; acc[5] += xv * r1.y; acc[6] += xv * r1.z; acc[7] += xv * r1.w;
    }
#pragma unroll
    for (int e = 0; e < 8; e++)
#pragma unroll
        for (int o = 16; o > 0; o >>= 1)
            acc[e] += __shfl_xor_sync(0xffffffffu, acc[e], o);

    if (lane == 0) {
        float m = acc[0];
#pragma unroll
        for (int e = 1; e < 8; e++) m = fmaxf(m, acc[e]);
        float p[8];
#pragma unroll
        for (int e = 0; e < 8; e++) p[e] = expf(acc[e] - m);
        int i0 = 0; float b0 = p[0];
#pragma unroll
        for (int e = 1; e < 8; e++) if (p[e] > b0) { b0 = p[e]; i0 = e; }
        int i1 = -1; float b1 = -1.f;
#pragma unroll
        for (int e = 0; e < 8; e++) if (e != i0 && p[e] > b1) { b1 = p[e]; i1 = e; }
        float inv = 1.f / (b0 + b1);
        int s0 = atomicAdd(&g_cnt[i0], 1); g_tok[i0 * Tt + s0] = t;
        int s1 = atomicAdd(&g_cnt[i1], 1); g_tok[i1 * Tt + s1] = t;
        g_sel[t] = make_int4(i0, s0, i1, s1);
        g_wt[t]  = make_float2(b0 * inv, b1 * inv);
    }
}

__global__ void scan_kernel() {
    if (threadIdx.x == 0) {
        int o = 0;
        for (int e = 0; e < Ee; e++) { g_off[e] = o; o += g_cnt[e]; }
    }
}

// per token: write tf32(x[t]) to g_xtf[t] and to its two expert slots in g_xg
__global__ void gather_kernel(const float* __restrict__ x) {
    int t = blockIdx.x;
    int4 s = g_sel[t];
    size_t p0 = (size_t)(g_off[s.x] + s.y) * Hh;
    size_t p1 = (size_t)(g_off[s.z] + s.w) * Hh;
    int i = threadIdx.x;               // 256 threads x float4 = 1024
    float4 v = *(const float4*)(x + (size_t)t * Hh + i * 4);
    v.x = __uint_as_float(f2tf(v.x));
    v.y = __uint_as_float(f2tf(v.y));
    v.z = __uint_as_float(f2tf(v.z));
    v.w = __uint_as_float(f2tf(v.w));
    *(float4*)(g_xtf + (size_t)t * Hh + i * 4) = v;
    *(float4*)(g_xg + p0 + i * 4) = v;
    *(float4*)(g_xg + p1 + i * 4) = v;
}

// ---------------- grouped GEMM, cp.async 2-stage pipeline ----------------
// MODE 1: g_mid = tf32(silu(A @ W1)),  A = g_xtf (base) / g_xg+off (expert), K=H, N=F
// MODE 2: out   = A @ W2,              A = g_mid rows,                      K=F, N=H
#define AS_W (128 * 36)
#define BS_W (32 * 136)

template <int MODE>
__global__ void __launch_bounds__(256, 2) gemm_kernel(
    float* __restrict__ Dout,
    const float* __restrict__ Wbase,
    const float* __restrict__ Wexp)
{
    constexpr int Kd = (MODE == 1) ? Hh : Ff;
    constexpr int Nd = (MODE == 1) ? Ff : Hh;
    constexpr int NT = Kd / 32;

    extern __shared__ unsigned sm[];
    unsigned* As = sm;              // 2 stages x AS_W
    unsigned* Bs = sm + 2 * AS_W;   // 2 stages x BS_W

    const int g  = blockIdx.z;
    const int tm = blockIdx.x;
    const int tn = blockIdx.y;
    const int e  = g - 1;
    const int cnt = (g == 0) ? Tt : g_cnt[e];
    if (tm * 128 >= cnt) return;
    const int off = (g == 0) ? 0 : g_off[e];

    const float* Bsrc = (g == 0) ? Wbase : (Wexp + (size_t)e * Kd * Nd);
    const float* Abase;
    float* Outp;
    if (MODE == 1) {
        Abase = (g == 0) ? g_xtf : (g_xg + (size_t)off * Hh);
        Outp  = g_mid + ((g == 0) ? 0 : (size_t)(Tt + off) * Ff);
    } else {
        Abase = g_mid + ((g == 0) ? 0 : (size_t)(Tt + off) * Ff);
        Outp  = (g == 0) ? Dout : (g_expout + (size_t)off * Hh);
    }

    const int tid  = threadIdx.x;
    const int lane = tid & 31;
    const int wid  = tid >> 5;
    const int wm = wid & 1, wn = wid >> 1;   // warps: 2(m) x 4(n), warp tile 64x32
    const int g8 = lane >> 2, tq = lane & 3;

    // ---- loader setup ----
    const int ar  = tid >> 3;          // A: 32 rows/pass, 4 passes
    const int ac  = (tid & 7) * 4;
    const int bkr = tid >> 5;          // B: 8 k-rows/pass, 4 passes
    const int bc  = (tid & 31) * 4;

    const float* aptr[4];
    int asz[4];
#pragma unroll
    for (int p = 0; p < 4; p++) {
        int row = tm * 128 + p * 32 + ar;
        int ok = row < cnt;
        aptr[p] = Abase + (size_t)(ok ? row : 0) * Kd + ac;
        asz[p] = ok ? 16 : 0;
    }
    const float* bptr = Bsrc + (size_t)bkr * Nd + tn * 128 + bc;

    unsigned a_dst, b_dst;
    {
        unsigned base = (unsigned)__cvta_generic_to_shared(sm);
        a_dst = base + (ar * 36 + ac) * 4;
        b_dst = base + (2 * AS_W + bkr * 136 + bc) * 4;
    }

    auto issue = [&](int stage, int kidx) {
        unsigned ad = a_dst + stage * (AS_W * 4);
        unsigned bd = b_dst + stage * (BS_W * 4);
        int akoff = kidx * 32;
        size_t bkoff = (size_t)kidx * 32 * Nd;
#pragma unroll
        for (int p = 0; p < 4; p++)
            cp16(ad + p * (32 * 36 * 4), aptr[p] + akoff, asz[p]);
#pragma unroll
        for (int p = 0; p < 4; p++)
            cp16(bd + p * (8 * 136 * 4), bptr + bkoff + (size_t)p * 8 * Nd, 16);
        cp_commit();
    };

    issue(0, 0);
    issue(1, 1);

    float C[4][4][4];
#pragma unroll
    for (int i = 0; i < 4; i++)
#pragma unroll
        for (int j = 0; j < 4; j++)
#pragma unroll
            for (int q = 0; q < 4; q++) C[i][j][q] = 0.f;

#pragma unroll 1
    for (int it = 0; it < NT; it++) {
        cp_wait<1>();
        __syncthreads();

        const unsigned* Asl = As + (it & 1) * AS_W;
        const unsigned* Bsl = Bs + (it & 1) * BS_W;

#pragma unroll
        for (int kk = 0; kk < 32; kk += 8) {
            unsigned a[4][4], b[4][2];
#pragma unroll
            for (int i = 0; i < 4; i++) {
                int r = wm * 64 + i * 16 + g8;
                a[i][0] = Asl[r * 36 + kk + tq];
                a[i][1] = Asl[(r + 8) * 36 + kk + tq];
                a[i][2] = Asl[r * 36 + kk + tq + 4];
                a[i][3] = Asl[(r + 8) * 36 + kk + tq + 4];
            }
#pragma unroll
            for (int j = 0; j < 4; j++) {
                int cc = wn * 32 + j * 8 + g8;
                b[j][0] = f2tf_u(Bsl[(kk + tq) * 136 + cc]);
                b[j][1] = f2tf_u(Bsl[(kk + tq + 4) * 136 + cc]);
            }
#pragma unroll
            for (int i = 0; i < 4; i++)
#pragma unroll
                for (int j = 0; j < 4; j++)
                    mma8(C[i][j], a[i], b[j]);
        }

        __syncthreads();
        if (it + 2 < NT) issue(it & 1, it + 2);
    }

    // ---- epilogue (rows are GLOBAL: tile offset tm*128 + local row) ----
#pragma unroll
    for (int i = 0; i < 4; i++) {
        int r0 = tm * 128 + wm * 64 + i * 16 + g8;   // global row of C[i][j][0..1]
        int r1 = r0 + 8;                              // global row of C[i][j][2..3]
        int ok0 = r0 < cnt;
        int ok1 = r1 < cnt;
#pragma unroll
        for (int j = 0; j < 4; j++) {
            int col = tn * 128 + wn * 32 + j * 8 + 2 * tq;
            float v0 = C[i][j][0], v1 = C[i][j][1];
            float v2 = C[i][j][2], v3 = C[i][j][3];
            if (MODE == 1) {
                v0 = __uint_as_float(f2tf(v0 / (1.f + __expf(-v0))));
                v1 = __uint_as_float(f2tf(v1 / (1.f + __expf(-v1))));
                v2 = __uint_as_float(f2tf(v2 / (1.f + __expf(-v2))));
                v3 = __uint_as_float(f2tf(v3 / (1.f + __expf(-v3))));
            }
            if (ok0) *(float2*)(Outp + (size_t)r0 * Nd + col) = make_float2(v0, v1);
            if (ok1) *(float2*)(Outp + (size_t)r1 * Nd + col) = make_float2(v2, v3);
        }
    }
}

// out[t] += w0*expout[p0] + w1*expout[p1]
__global__ void combine_kernel(float* __restrict__ out) {
    int t = blockIdx.x;
    int4 s = g_sel[t];
    float2 w = g_wt[t];
    int p0 = g_off[s.x] + s.y;
    int p1 = g_off[s.z] + s.w;
    const float4* a = (const float4*)(g_expout + (size_t)p0 * Hh);
    const float4* b = (const float4*)(g_expout + (size_t)p1 * Hh);
    float4* o = (float4*)(out + (size_t)t * Hh);
    int i = threadIdx.x;
    float4 ov = o[i], av = a[i], bv = b[i];
    ov.x += w.x * av.x + w.y * bv.x;
    ov.y += w.x * av.y + w.y * bv.y;
    ov.z += w.x * av.z + w.y * bv.z;
    ov.w += w.x * av.w + w.y * bv.w;
    o[i] = ov;
}

// ---------------- launch ----------------
extern "C" void kernel_launch(void* const* d_in, const int* in_sizes, int n_in,
                              void* d_out, int out_size)
{
    const float* x   = (const float*)d_in[0];
    const float* rw  = (const float*)d_in[1];
    const float* bw1 = (const float*)d_in[2];
    const float* bw2 = (const float*)d_in[3];
    const float* ew1 = (const float*)d_in[4];
    const float* ew2 = (const float*)d_in[5];
    float* out = (float*)d_out;

    // Idempotent, not a stream op; called unconditionally (no static guards).
    const int smem_bytes = (2 * AS_W + 2 * BS_W) * 4;   // ~71.7 KB
    cudaFuncSetAttribute(gemm_kernel<1>, cudaFuncAttributeMaxDynamicSharedMemorySize, smem_bytes);
    cudaFuncSetAttribute(gemm_kernel<2>, cudaFuncAttributeMaxDynamicSharedMemorySize, smem_bytes);

    zero_cnt_kernel<<<1, 32>>>();
    router_kernel<<<Tt / 8, 256>>>(x, rw);
    scan_kernel<<<1, 32>>>();
    gather_kernel<<<Tt, 256>>>(x);

    gemm_kernel<1><<<dim3(32, Ff / 128, Ee + 1), 256, smem_bytes>>>(nullptr, bw1, ew1);
    gemm_kernel<2><<<dim3(32, Hh / 128, Ee + 1), 256, smem_bytes>>>(out, bw2, ew2);

    combine_kernel<<<Tt, 256>>>(out);
}